// round 1
// baseline (speedup 1.0000x reference)
#include <cuda_runtime.h>
#include <math.h>

// Problem constants
#define BATCH 4
#define SEQ   2048
#define DM    2048
#define NH    16
#define DH    128
#define RH    64               // rotary half-dim
#define NTOK  (BATCH*SEQ)      // 8192
#define QKVN  (3*DM)           // 6144

// ---------------- scratch (device globals; no allocation allowed) -----------
__device__ float g_qkv[(size_t)NTOK * QKVN];          // 8192 x 6144
__device__ float g_q  [(size_t)BATCH*NH*SEQ*DH];      // [b,h,s,d]
__device__ float g_k  [(size_t)BATCH*NH*SEQ*DH];
__device__ float g_v  [(size_t)BATCH*NH*SEQ*DH];
__device__ float g_att[(size_t)NTOK * DM];            // [b,s,h*dh]

// ---------------- generic tiled SGEMM + bias --------------------------------
// C[M,N] = A[M,K] @ B[K,N] + bias[N].  BM=BN=128, BK=16, 256 thr, 8x8 microtile
// thread (ty,tx): rows {ty+16i}, cols {tx+16j}  (strided => coalesced C stores)
__global__ __launch_bounds__(256)
void sgemm_bias(const float* __restrict__ A, const float* __restrict__ Bw,
                const float* __restrict__ bias, float* __restrict__ C,
                int M, int N, int K)
{
    __shared__ float As[16][132];   // padded: transposed A tile [k][m]
    __shared__ float Bs[16][128];   // [k][n]

    const int tid = threadIdx.x;
    const int tx  = tid & 15;
    const int ty  = tid >> 4;
    const int bm  = blockIdx.y * 128;
    const int bn  = blockIdx.x * 128;

    float acc[8][8];
#pragma unroll
    for (int i = 0; i < 8; i++)
#pragma unroll
        for (int j = 0; j < 8; j++) acc[i][j] = 0.f;

    for (int kt = 0; kt < K; kt += 16) {
        // A tile: 128 rows x 16 cols  (512 float4, 2 per thread)
#pragma unroll
        for (int q = 0; q < 2; q++) {
            int idx = q * 256 + tid;
            int row = idx >> 2, c4 = idx & 3;
            const float4 a = *(const float4*)(A + (size_t)(bm + row) * K + kt + c4 * 4);
            As[c4*4+0][row] = a.x;  As[c4*4+1][row] = a.y;
            As[c4*4+2][row] = a.z;  As[c4*4+3][row] = a.w;
        }
        // B tile: 16 rows x 128 cols (512 float4, 2 per thread)
#pragma unroll
        for (int q = 0; q < 2; q++) {
            int idx = q * 256 + tid;
            int row = idx >> 5, c4 = idx & 31;
            *(float4*)(&Bs[row][c4*4]) =
                *(const float4*)(Bw + (size_t)(kt + row) * N + bn + c4 * 4);
        }
        __syncthreads();

#pragma unroll
        for (int k = 0; k < 16; k++) {
            float ar[8], br[8];
#pragma unroll
            for (int i = 0; i < 8; i++) ar[i] = As[k][i * 16 + ty];
#pragma unroll
            for (int j = 0; j < 8; j++) br[j] = Bs[k][j * 16 + tx];
#pragma unroll
            for (int i = 0; i < 8; i++)
#pragma unroll
                for (int j = 0; j < 8; j++)
                    acc[i][j] = fmaf(ar[i], br[j], acc[i][j]);
        }
        __syncthreads();
    }

#pragma unroll
    for (int j = 0; j < 8; j++) {
        const float bj = bias[bn + j * 16 + tx];
#pragma unroll
        for (int i = 0; i < 8; i++)
            C[(size_t)(bm + i * 16 + ty) * N + bn + j * 16 + tx] = acc[i][j] + bj;
    }
}

// ---------------- RoPE + split/transpose ------------------------------------
// one thread per (b,h,s,pair j)
__global__ void rope_split(const float* __restrict__ qkv,
                           const float* __restrict__ rc,
                           const float* __restrict__ rs)
{
    const int idx = blockIdx.x * blockDim.x + threadIdx.x;   // B*H*S*RH = 2^23
    const int j = idx & (RH - 1);
    const int s = (idx >> 6) & (SEQ - 1);
    const int h = (idx >> 17) & (NH - 1);
    const int b = idx >> 21;

    const float* row = qkv + (size_t)(b * SEQ + s) * QKVN;
    const float c  = rc[s * RH + j];
    const float sn = rs[s * RH + j];
    const int col = h * DH + 2 * j;

    const float qe = row[col],          qo = row[col + 1];
    const float ke = row[DM + col],     ko = row[DM + col + 1];
    const float ve = row[2 * DM + col], vo = row[2 * DM + col + 1];

    const size_t o = ((size_t)((b * NH + h) * SEQ + s)) * DH + 2 * j;
    g_q[o]     = qe * c - qo * sn;
    g_q[o + 1] = qe * sn + qo * c;
    g_k[o]     = ke * c - ko * sn;
    g_k[o + 1] = ke * sn + ko * c;
    g_v[o]     = ve;
    g_v[o + 1] = vo;
}

// ---------------- streaming-softmax attention -------------------------------
#define BQ 64
#define BKV 64
#define QS 129   // padded strides (bank-conflict free)
#define KS 129
#define VS 128
#define PS 65
#define ATTN_SMEM ((BQ*QS + BKV*KS + BKV*VS + BQ*PS) * (int)sizeof(float))  // 115456

__global__ __launch_bounds__(256)
void attn_kernel(float* __restrict__ out)
{
    extern __shared__ float sm[];
    float* Qs = sm;
    float* Ks = Qs + BQ * QS;
    float* Vs = Ks + BKV * KS;
    float* Ps = Vs + BKV * VS;

    const int qb = blockIdx.x, h = blockIdx.y, b = blockIdx.z;
    const int tid = threadIdx.x;
    const int tx = tid & 15, ty = tid >> 4;
    const float scale = 0.08838834764831845f;  // 1/sqrt(128)
    const size_t base = ((size_t)(b * NH + h)) * SEQ * DH;

    // load Q tile (pre-scaled), 64x128: 2048 float4, 8 per thread
#pragma unroll
    for (int q = 0; q < 8; q++) {
        int idx = q * 256 + tid;
        int row = idx >> 5, c4 = idx & 31;
        float4 v = *(const float4*)(g_q + base + (size_t)(qb * BQ + row) * DH + c4 * 4);
        float* dst = Qs + row * QS + c4 * 4;
        dst[0] = v.x * scale; dst[1] = v.y * scale;
        dst[2] = v.z * scale; dst[3] = v.w * scale;
    }

    float m[4], l[4], o[4][8];
#pragma unroll
    for (int i = 0; i < 4; i++) {
        m[i] = -1e30f; l[i] = 0.f;
#pragma unroll
        for (int j = 0; j < 8; j++) o[i][j] = 0.f;
    }

    for (int kb = 0; kb <= qb; kb++) {
        __syncthreads();   // previous Ps/Vs consumers done
        // load K,V tiles
#pragma unroll
        for (int q = 0; q < 8; q++) {
            int idx = q * 256 + tid;
            int row = idx >> 5, c4 = idx & 31;
            const size_t g = base + (size_t)(kb * BKV + row) * DH + c4 * 4;
            float4 kv = *(const float4*)(g_k + g);
            float* kd = Ks + row * KS + c4 * 4;
            kd[0] = kv.x; kd[1] = kv.y; kd[2] = kv.z; kd[3] = kv.w;
            *(float4*)(Vs + row * VS + c4 * 4) = *(const float4*)(g_v + g);
        }
        __syncthreads();

        // scores: 4x4 microtile, rows i*16+ty, cols j*16+tx
        float sc[4][4];
#pragma unroll
        for (int i = 0; i < 4; i++)
#pragma unroll
            for (int j = 0; j < 4; j++) sc[i][j] = 0.f;

#pragma unroll 4
        for (int d = 0; d < DH; d++) {
            float qr[4], kr[4];
#pragma unroll
            for (int i = 0; i < 4; i++) qr[i] = Qs[(i * 16 + ty) * QS + d];
#pragma unroll
            for (int j = 0; j < 4; j++) kr[j] = Ks[(j * 16 + tx) * KS + d];
#pragma unroll
            for (int i = 0; i < 4; i++)
#pragma unroll
                for (int j = 0; j < 4; j++)
                    sc[i][j] = fmaf(qr[i], kr[j], sc[i][j]);
        }

        // causal mask (only the diagonal block has masked entries)
        if (kb == qb) {
#pragma unroll
            for (int i = 0; i < 4; i++) {
                const int qi = i * 16 + ty;
#pragma unroll
                for (int j = 0; j < 4; j++)
                    if ((j * 16 + tx) > qi) sc[i][j] = -1e30f;
            }
        }

        // online softmax update
#pragma unroll
        for (int i = 0; i < 4; i++) {
            float rm = sc[i][0];
#pragma unroll
            for (int j = 1; j < 4; j++) rm = fmaxf(rm, sc[i][j]);
#pragma unroll
            for (int off = 8; off >= 1; off >>= 1)
                rm = fmaxf(rm, __shfl_xor_sync(0xffffffffu, rm, off));
            const float mn = fmaxf(m[i], rm);
            const float alpha = __expf(m[i] - mn);
            m[i] = mn;
            float rsum = 0.f;
#pragma unroll
            for (int j = 0; j < 4; j++) {
                const float p = __expf(sc[i][j] - mn);
                Ps[(i * 16 + ty) * PS + j * 16 + tx] = p;
                rsum += p;
            }
#pragma unroll
            for (int off = 8; off >= 1; off >>= 1)
                rsum += __shfl_xor_sync(0xffffffffu, rsum, off);
            l[i] = l[i] * alpha + rsum;
#pragma unroll
            for (int j = 0; j < 8; j++) o[i][j] *= alpha;
        }
        __syncthreads();  // Ps visible to all

        // O += P @ V   (rows i*16+ty, cols j*16+tx)
#pragma unroll 4
        for (int kk = 0; kk < BKV; kk++) {
            float pr[4], vr[8];
#pragma unroll
            for (int i = 0; i < 4; i++) pr[i] = Ps[(i * 16 + ty) * PS + kk];
#pragma unroll
            for (int j = 0; j < 8; j++) vr[j] = Vs[kk * VS + j * 16 + tx];
#pragma unroll
            for (int i = 0; i < 4; i++)
#pragma unroll
                for (int j = 0; j < 8; j++)
                    o[i][j] = fmaf(pr[i], vr[j], o[i][j]);
        }
    }

    // epilogue: normalize, write to [b, s, h*DH + d]
#pragma unroll
    for (int i = 0; i < 4; i++) {
        const float inv = 1.f / l[i];
        const size_t r = (size_t)(b * SEQ + qb * BQ + i * 16 + ty) * DM + h * DH;
#pragma unroll
        for (int j = 0; j < 8; j++)
            out[r + j * 16 + tx] = o[i][j] * inv;
    }
}

// ---------------- launch -----------------------------------------------------
extern "C" void kernel_launch(void* const* d_in, const int* in_sizes, int n_in,
                              void* d_out, int out_size)
{
    const float* x     = (const float*)d_in[0];
    const float* w_qkv = (const float*)d_in[1];
    const float* b_qkv = (const float*)d_in[2];
    const float* w_out = (const float*)d_in[3];
    const float* b_out = (const float*)d_in[4];
    const float* rc    = (const float*)d_in[5];
    const float* rs    = (const float*)d_in[6];
    float* out = (float*)d_out;

    float *p_qkv, *p_att;
    cudaGetSymbolAddress((void**)&p_qkv, g_qkv);
    cudaGetSymbolAddress((void**)&p_att, g_att);

    cudaFuncSetAttribute(attn_kernel,
                         cudaFuncAttributeMaxDynamicSharedMemorySize, ATTN_SMEM);

    // 1) qkv = x @ w_qkv + b_qkv
    sgemm_bias<<<dim3(QKVN / 128, NTOK / 128), 256>>>(x, w_qkv, b_qkv, p_qkv,
                                                      NTOK, QKVN, DM);
    // 2) RoPE + split to [b,h,s,d]
    rope_split<<<(BATCH * NH * SEQ * RH) / 256, 256>>>(p_qkv, rc, rs);
    // 3) causal attention -> [b,s,d]
    attn_kernel<<<dim3(SEQ / BQ, NH, BATCH), 256, ATTN_SMEM>>>(p_att);
    // 4) out = att @ w_out + b_out
    sgemm_bias<<<dim3(DM / 128, NTOK / 128), 256>>>(p_att, w_out, b_out, out,
                                                    NTOK, DM, DM);
}

// round 3
// speedup vs baseline: 1.7819x; 1.7819x over previous
#include <cuda_runtime.h>
#include <cuda_bf16.h>
#include <cstdint>
#include <math.h>

// Problem constants
#define BATCH 4
#define SEQ   2048
#define DM    2048
#define NH    16
#define DH    128
#define RH    64
#define NTOK  (BATCH*SEQ)      // 8192
#define QKVN  (3*DM)           // 6144

// ---------------- scratch (device globals) ----------------------------------
__device__ float g_qkv[(size_t)NTOK * QKVN];
__device__ float g_q  [(size_t)BATCH*NH*SEQ*DH];
__device__ float g_k  [(size_t)BATCH*NH*SEQ*DH];
__device__ float g_v  [(size_t)BATCH*NH*SEQ*DH];
__device__ float g_att[(size_t)NTOK * DM];

__device__ __nv_bfloat16 g_xhi[(size_t)NTOK*DM];
__device__ __nv_bfloat16 g_xlo[(size_t)NTOK*DM];
__device__ __nv_bfloat16 g_ahi[(size_t)NTOK*DM];
__device__ __nv_bfloat16 g_alo[(size_t)NTOK*DM];
__device__ __nv_bfloat16 g_wqkvT_hi[(size_t)QKVN*DM];
__device__ __nv_bfloat16 g_wqkvT_lo[(size_t)QKVN*DM];
__device__ __nv_bfloat16 g_woutT_hi[(size_t)DM*DM];
__device__ __nv_bfloat16 g_woutT_lo[(size_t)DM*DM];

// ---------------- PTX helpers (baseline compute_103 only) --------------------
__device__ __forceinline__ uint32_t smem_u32(const void* p) {
    uint32_t a;
    asm("{ .reg .u64 t; cvta.to.shared.u64 t, %1; cvt.u32.u64 %0, t; }" : "=r"(a) : "l"(p));
    return a;
}
#define CP_ASYNC16(dst, src) \
    asm volatile("cp.async.cg.shared.global [%0], [%1], 16;" :: "r"(dst), "l"(src))
#define CP_COMMIT() asm volatile("cp.async.commit_group;" ::: "memory")
#define CP_WAIT(n)  asm volatile("cp.async.wait_group %0;" :: "n"(n) : "memory")

__device__ __forceinline__ void ldsm_x4(uint32_t* r, uint32_t addr) {
    asm volatile("ldmatrix.sync.aligned.m8n8.x4.shared.b16 {%0,%1,%2,%3}, [%4];"
        : "=r"(r[0]), "=r"(r[1]), "=r"(r[2]), "=r"(r[3]) : "r"(addr));
}
__device__ __forceinline__ void mma_bf16(float* d, const uint32_t* a,
                                         uint32_t b0, uint32_t b1) {
    asm volatile("mma.sync.aligned.m16n8k16.row.col.f32.bf16.bf16.f32 "
        "{%0,%1,%2,%3}, {%4,%5,%6,%7}, {%8,%9}, {%0,%1,%2,%3};"
        : "+f"(d[0]), "+f"(d[1]), "+f"(d[2]), "+f"(d[3])
        : "r"(a[0]), "r"(a[1]), "r"(a[2]), "r"(a[3]), "r"(b0), "r"(b1));
}

// ---------------- split / transpose-split kernels ----------------------------
__global__ void split_a(const float* __restrict__ in,
                        __nv_bfloat16* __restrict__ hi,
                        __nv_bfloat16* __restrict__ lo, int n4)
{
    int i = blockIdx.x * blockDim.x + threadIdx.x;
    if (i >= n4) return;
    float4 v = ((const float4*)in)[i];
    __nv_bfloat16 h0 = __float2bfloat16(v.x), h1 = __float2bfloat16(v.y);
    __nv_bfloat16 h2 = __float2bfloat16(v.z), h3 = __float2bfloat16(v.w);
    __nv_bfloat16 l0 = __float2bfloat16(v.x - __bfloat162float(h0));
    __nv_bfloat16 l1 = __float2bfloat16(v.y - __bfloat162float(h1));
    __nv_bfloat16 l2 = __float2bfloat16(v.z - __bfloat162float(h2));
    __nv_bfloat16 l3 = __float2bfloat16(v.w - __bfloat162float(h3));
    ((__nv_bfloat162*)hi)[i*2]   = __nv_bfloat162(h0, h1);
    ((__nv_bfloat162*)hi)[i*2+1] = __nv_bfloat162(h2, h3);
    ((__nv_bfloat162*)lo)[i*2]   = __nv_bfloat162(l0, l1);
    ((__nv_bfloat162*)lo)[i*2+1] = __nv_bfloat162(l2, l3);
}

// W[R,C] fp32 -> T[C,R] bf16 hi/lo
__global__ void transpose_split(const float* __restrict__ W,
                                __nv_bfloat16* __restrict__ Thi,
                                __nv_bfloat16* __restrict__ Tlo, int R, int C)
{
    __shared__ float t[32][33];
    int c0 = blockIdx.x * 32, r0 = blockIdx.y * 32;
    int tx = threadIdx.x, ty = threadIdx.y;
#pragma unroll
    for (int j = 0; j < 4; j++)
        t[ty + j*8][tx] = W[(size_t)(r0 + ty + j*8) * C + c0 + tx];
    __syncthreads();
#pragma unroll
    for (int j = 0; j < 4; j++) {
        int cc = c0 + ty + j*8;
        float v = t[tx][ty + j*8];
        __nv_bfloat16 h = __float2bfloat16(v);
        __nv_bfloat16 l = __float2bfloat16(v - __bfloat162float(h));
        Thi[(size_t)cc * R + r0 + tx] = h;
        Tlo[(size_t)cc * R + r0 + tx] = l;
    }
}

// ---------------- bf16x3 GEMM via mma.sync (HMMA) ----------------------------
// C[M,N] = A[M,K] @ B^T (B stored [N,K] K-major) + bias.
// 128x128 CTA tile, 8 warps (2x4), warp tile 64x32, K-chunk 32, double-buffered.
#define TK 32
#define STR 80                 // smem row stride in bytes (32 bf16 + 8 pad)
#define T_TILE (128*STR)       // 10240
#define STAGE  (4*T_TILE)      // Ahi, Alo, Bhi, Blo = 40960
#define GEMM_SMEM (2*STAGE)    // 81920

__global__ __launch_bounds__(256)
void gemm_tc(const __nv_bfloat16* __restrict__ Ahi, const __nv_bfloat16* __restrict__ Alo,
             const __nv_bfloat16* __restrict__ Bhi, const __nv_bfloat16* __restrict__ Blo,
             const float* __restrict__ bias, float* __restrict__ C,
             int M, int N, int K)
{
    extern __shared__ char sm[];
    const uint32_t sbase = smem_u32(sm);

    const int tid = threadIdx.x;
    const int wid = tid >> 5;
    const int lane = tid & 31;
    const int warpM = wid >> 2;       // 0..1
    const int warpN = wid & 3;        // 0..3
    const int bn = blockIdx.x * 128;
    const int bm = blockIdx.y * 128;

    const __nv_bfloat16* srcs[4] = {Ahi, Alo, Bhi, Blo};
    const int rowb[4] = {bm, bm, bn, bn};

    float acc[4][4][4];
#pragma unroll
    for (int mi = 0; mi < 4; mi++)
#pragma unroll
        for (int ni = 0; ni < 4; ni++)
#pragma unroll
            for (int r = 0; r < 4; r++) acc[mi][ni][r] = 0.f;

    const int NI = K / TK;

    // prefetch stage 0
    {
        const int kt = 0;
        const uint32_t st = sbase;
#pragma unroll
        for (int it = 0; it < 8; it++) {
            int idx = it * 256 + tid;
            int t = idx >> 9, rem = idx & 511, r = rem >> 2, c = rem & 3;
            uint32_t dst = st + t * T_TILE + r * STR + c * 16;
            const void* src = srcs[t] + (size_t)(rowb[t] + r) * K + kt + c * 8;
            CP_ASYNC16(dst, src);
        }
        CP_COMMIT();
    }

    for (int i = 0; i < NI; i++) {
        if (i + 1 < NI) {   // prefetch next stage into other buffer
            const int kt = (i + 1) * TK;
            const uint32_t st = sbase + ((i + 1) & 1) * STAGE;
#pragma unroll
            for (int it = 0; it < 8; it++) {
                int idx = it * 256 + tid;
                int t = idx >> 9, rem = idx & 511, r = rem >> 2, c = rem & 3;
                uint32_t dst = st + t * T_TILE + r * STR + c * 16;
                const void* src = srcs[t] + (size_t)(rowb[t] + r) * K + kt + c * 8;
                CP_ASYNC16(dst, src);
            }
            CP_COMMIT();
            CP_WAIT(1);     // stage i complete (next still in flight)
        } else {
            CP_WAIT(0);
        }
        __syncthreads();    // stage i visible to all warps

        const uint32_t st = sbase + (i & 1) * STAGE;
        const uint32_t Ah = st, Al = st + T_TILE;
        const uint32_t Bh = st + 2 * T_TILE, Bl = st + 3 * T_TILE;

#pragma unroll
        for (int ks = 0; ks < 2; ks++) {
            const uint32_t ko = ks * 32 + (lane >> 4) * 16;   // byte col within row
            const uint32_t arow = (warpM * 64 + (lane & 15)) * STR + ko;
            const uint32_t brow = (warpN * 32 + (lane & 15)) * STR + ko;

            uint32_t ahf[4][4], alf[4][4], bhf[2][4], blf[2][4];
#pragma unroll
            for (int mi = 0; mi < 4; mi++) {
                ldsm_x4(ahf[mi], Ah + arow + mi * 16 * STR);
                ldsm_x4(alf[mi], Al + arow + mi * 16 * STR);
            }
#pragma unroll
            for (int pi = 0; pi < 2; pi++) {
                ldsm_x4(bhf[pi], Bh + brow + pi * 16 * STR);
                ldsm_x4(blf[pi], Bl + brow + pi * 16 * STR);
            }
#pragma unroll
            for (int mi = 0; mi < 4; mi++)
#pragma unroll
                for (int ni = 0; ni < 4; ni++) {
                    const int pi = ni >> 1, o = ni & 1;
                    mma_bf16(acc[mi][ni], ahf[mi], bhf[pi][o], bhf[pi][o + 2]);
                    mma_bf16(acc[mi][ni], ahf[mi], blf[pi][o], blf[pi][o + 2]);
                    mma_bf16(acc[mi][ni], alf[mi], bhf[pi][o], bhf[pi][o + 2]);
                }
        }
        __syncthreads();    // all warps done reading stage i before it's reused
    }

    // epilogue: fragment layout -> C + bias
#pragma unroll
    for (int mi = 0; mi < 4; mi++) {
        const int r0 = bm + warpM * 64 + mi * 16 + (lane >> 2);
#pragma unroll
        for (int ni = 0; ni < 4; ni++) {
            const int c0 = bn + warpN * 32 + ni * 8 + (lane & 3) * 2;
            const float b0 = bias[c0], b1 = bias[c0 + 1];
            float2 v0 = make_float2(acc[mi][ni][0] + b0, acc[mi][ni][1] + b1);
            float2 v1 = make_float2(acc[mi][ni][2] + b0, acc[mi][ni][3] + b1);
            *(float2*)(C + (size_t)r0 * N + c0) = v0;
            *(float2*)(C + (size_t)(r0 + 8) * N + c0) = v1;
        }
    }
}

// ---------------- RoPE + split/transpose ------------------------------------
__global__ void rope_split(const float* __restrict__ qkv,
                           const float* __restrict__ rc,
                           const float* __restrict__ rs)
{
    const int idx = blockIdx.x * blockDim.x + threadIdx.x;
    const int j = idx & (RH - 1);
    const int s = (idx >> 6) & (SEQ - 1);
    const int h = (idx >> 17) & (NH - 1);
    const int b = idx >> 21;

    const float* row = qkv + (size_t)(b * SEQ + s) * QKVN;
    const float c  = rc[s * RH + j];
    const float sn = rs[s * RH + j];
    const int col = h * DH + 2 * j;

    const float qe = row[col],          qo = row[col + 1];
    const float ke = row[DM + col],     ko = row[DM + col + 1];
    const float ve = row[2 * DM + col], vo = row[2 * DM + col + 1];

    const size_t o = ((size_t)((b * NH + h) * SEQ + s)) * DH + 2 * j;
    g_q[o]     = qe * c - qo * sn;
    g_q[o + 1] = qe * sn + qo * c;
    g_k[o]     = ke * c - ko * sn;
    g_k[o + 1] = ke * sn + ko * c;
    g_v[o]     = ve;
    g_v[o + 1] = vo;
}

// ---------------- streaming-softmax attention -------------------------------
#define BQ 64
#define BKV 64
#define QS 129
#define KS 129
#define VS 128
#define PS 65
#define ATTN_SMEM ((BQ*QS + BKV*KS + BKV*VS + BQ*PS) * (int)sizeof(float))

__global__ __launch_bounds__(256)
void attn_kernel(float* __restrict__ out)
{
    extern __shared__ float smf[];
    float* Qs = smf;
    float* Ks = Qs + BQ * QS;
    float* Vs = Ks + BKV * KS;
    float* Ps = Vs + BKV * VS;

    const int qb = blockIdx.x, h = blockIdx.y, b = blockIdx.z;
    const int tid = threadIdx.x;
    const int tx = tid & 15, ty = tid >> 4;
    const float scale = 0.08838834764831845f;
    const size_t base = ((size_t)(b * NH + h)) * SEQ * DH;

#pragma unroll
    for (int q = 0; q < 8; q++) {
        int idx = q * 256 + tid;
        int row = idx >> 5, c4 = idx & 31;
        float4 v = *(const float4*)(g_q + base + (size_t)(qb * BQ + row) * DH + c4 * 4);
        float* dst = Qs + row * QS + c4 * 4;
        dst[0] = v.x * scale; dst[1] = v.y * scale;
        dst[2] = v.z * scale; dst[3] = v.w * scale;
    }

    float m[4], l[4], o[4][8];
#pragma unroll
    for (int i = 0; i < 4; i++) {
        m[i] = -1e30f; l[i] = 0.f;
#pragma unroll
        for (int j = 0; j < 8; j++) o[i][j] = 0.f;
    }

    for (int kb = 0; kb <= qb; kb++) {
        __syncthreads();
#pragma unroll
        for (int q = 0; q < 8; q++) {
            int idx = q * 256 + tid;
            int row = idx >> 5, c4 = idx & 31;
            const size_t g = base + (size_t)(kb * BKV + row) * DH + c4 * 4;
            float4 kv = *(const float4*)(g_k + g);
            float* kd = Ks + row * KS + c4 * 4;
            kd[0] = kv.x; kd[1] = kv.y; kd[2] = kv.z; kd[3] = kv.w;
            *(float4*)(Vs + row * VS + c4 * 4) = *(const float4*)(g_v + g);
        }
        __syncthreads();

        float sc[4][4];
#pragma unroll
        for (int i = 0; i < 4; i++)
#pragma unroll
            for (int j = 0; j < 4; j++) sc[i][j] = 0.f;

#pragma unroll 4
        for (int d = 0; d < DH; d++) {
            float qr[4], kr[4];
#pragma unroll
            for (int i = 0; i < 4; i++) qr[i] = Qs[(i * 16 + ty) * QS + d];
#pragma unroll
            for (int j = 0; j < 4; j++) kr[j] = Ks[(j * 16 + tx) * KS + d];
#pragma unroll
            for (int i = 0; i < 4; i++)
#pragma unroll
                for (int j = 0; j < 4; j++)
                    sc[i][j] = fmaf(qr[i], kr[j], sc[i][j]);
        }

        if (kb == qb) {
#pragma unroll
            for (int i = 0; i < 4; i++) {
                const int qi = i * 16 + ty;
#pragma unroll
                for (int j = 0; j < 4; j++)
                    if ((j * 16 + tx) > qi) sc[i][j] = -1e30f;
            }
        }

#pragma unroll
        for (int i = 0; i < 4; i++) {
            float rm = sc[i][0];
#pragma unroll
            for (int j = 1; j < 4; j++) rm = fmaxf(rm, sc[i][j]);
#pragma unroll
            for (int off = 8; off >= 1; off >>= 1)
                rm = fmaxf(rm, __shfl_xor_sync(0xffffffffu, rm, off));
            const float mn = fmaxf(m[i], rm);
            const float alpha = __expf(m[i] - mn);
            m[i] = mn;
            float rsum = 0.f;
#pragma unroll
            for (int j = 0; j < 4; j++) {
                const float p = __expf(sc[i][j] - mn);
                Ps[(i * 16 + ty) * PS + j * 16 + tx] = p;
                rsum += p;
            }
#pragma unroll
            for (int off = 8; off >= 1; off >>= 1)
                rsum += __shfl_xor_sync(0xffffffffu, rsum, off);
            l[i] = l[i] * alpha + rsum;
#pragma unroll
            for (int j = 0; j < 8; j++) o[i][j] *= alpha;
        }
        __syncthreads();

#pragma unroll 4
        for (int kk = 0; kk < BKV; kk++) {
            float pr[4], vr[8];
#pragma unroll
            for (int i = 0; i < 4; i++) pr[i] = Ps[(i * 16 + ty) * PS + kk];
#pragma unroll
            for (int j = 0; j < 8; j++) vr[j] = Vs[kk * VS + j * 16 + tx];
#pragma unroll
            for (int i = 0; i < 4; i++)
#pragma unroll
                for (int j = 0; j < 8; j++)
                    o[i][j] = fmaf(pr[i], vr[j], o[i][j]);
        }
    }

#pragma unroll
    for (int i = 0; i < 4; i++) {
        const float inv = 1.f / l[i];
        const size_t r = (size_t)(b * SEQ + qb * BQ + i * 16 + ty) * DM + h * DH;
#pragma unroll
        for (int j = 0; j < 8; j++)
            out[r + j * 16 + tx] = o[i][j] * inv;
    }
}

// ---------------- launch -----------------------------------------------------
extern "C" void kernel_launch(void* const* d_in, const int* in_sizes, int n_in,
                              void* d_out, int out_size)
{
    const float* x     = (const float*)d_in[0];
    const float* w_qkv = (const float*)d_in[1];
    const float* b_qkv = (const float*)d_in[2];
    const float* w_out = (const float*)d_in[3];
    const float* b_out = (const float*)d_in[4];
    const float* rc    = (const float*)d_in[5];
    const float* rs    = (const float*)d_in[6];
    float* out = (float*)d_out;

    float *p_qkv, *p_att;
    __nv_bfloat16 *p_xhi, *p_xlo, *p_ahi, *p_alo;
    __nv_bfloat16 *p_wqh, *p_wql, *p_woh, *p_wol;
    cudaGetSymbolAddress((void**)&p_qkv, g_qkv);
    cudaGetSymbolAddress((void**)&p_att, g_att);
    cudaGetSymbolAddress((void**)&p_xhi, g_xhi);
    cudaGetSymbolAddress((void**)&p_xlo, g_xlo);
    cudaGetSymbolAddress((void**)&p_ahi, g_ahi);
    cudaGetSymbolAddress((void**)&p_alo, g_alo);
    cudaGetSymbolAddress((void**)&p_wqh, g_wqkvT_hi);
    cudaGetSymbolAddress((void**)&p_wql, g_wqkvT_lo);
    cudaGetSymbolAddress((void**)&p_woh, g_woutT_hi);
    cudaGetSymbolAddress((void**)&p_wol, g_woutT_lo);

    cudaFuncSetAttribute(attn_kernel,
                         cudaFuncAttributeMaxDynamicSharedMemorySize, ATTN_SMEM);
    cudaFuncSetAttribute(gemm_tc,
                         cudaFuncAttributeMaxDynamicSharedMemorySize, GEMM_SMEM);

    // 1) split x -> bf16 hi/lo
    {
        int n4 = NTOK * DM / 4;
        split_a<<<(n4 + 255) / 256, 256>>>(x, p_xhi, p_xlo, n4);
    }
    // 2) transpose+split weights
    transpose_split<<<dim3(QKVN / 32, DM / 32), dim3(32, 8)>>>(w_qkv, p_wqh, p_wql, DM, QKVN);
    transpose_split<<<dim3(DM / 32, DM / 32), dim3(32, 8)>>>(w_out, p_woh, p_wol, DM, DM);
    // 3) qkv = x @ w_qkv + b  (HMMA bf16x3)
    gemm_tc<<<dim3(QKVN / 128, NTOK / 128), 256, GEMM_SMEM>>>(
        p_xhi, p_xlo, p_wqh, p_wql, b_qkv, p_qkv, NTOK, QKVN, DM);
    // 4) RoPE + split heads
    rope_split<<<(BATCH * NH * SEQ * RH) / 256, 256>>>(p_qkv, rc, rs);
    // 5) causal attention
    attn_kernel<<<dim3(SEQ / BQ, NH, BATCH), 256, ATTN_SMEM>>>(p_att);
    // 6) split attention output
    {
        int n4 = NTOK * DM / 4;
        split_a<<<(n4 + 255) / 256, 256>>>(p_att, p_ahi, p_alo, n4);
    }
    // 7) out = att @ w_out + b  (HMMA bf16x3)
    gemm_tc<<<dim3(DM / 128, NTOK / 128), 256, GEMM_SMEM>>>(
        p_ahi, p_alo, p_woh, p_wol, b_out, out, NTOK, DM, DM);
}

// round 4
// speedup vs baseline: 2.7431x; 1.5394x over previous
#include <cuda_runtime.h>
#include <cuda_bf16.h>
#include <cstdint>
#include <math.h>

// Problem constants
#define BATCH 4
#define SEQ   2048
#define DM    2048
#define NH    16
#define DH    128
#define RH    64
#define NTOK  (BATCH*SEQ)      // 8192
#define QKVN  (3*DM)           // 6144
#define BH    (BATCH*NH)       // 64

// ---------------- scratch (device globals) ----------------------------------
__device__ float g_qkv[(size_t)NTOK * QKVN];

__device__ __nv_bfloat16 g_xhi[(size_t)NTOK*DM];
__device__ __nv_bfloat16 g_xlo[(size_t)NTOK*DM];
__device__ __nv_bfloat16 g_ahi[(size_t)NTOK*DM];
__device__ __nv_bfloat16 g_alo[(size_t)NTOK*DM];
__device__ __nv_bfloat16 g_wqkvT_hi[(size_t)QKVN*DM];
__device__ __nv_bfloat16 g_wqkvT_lo[(size_t)QKVN*DM];
__device__ __nv_bfloat16 g_woutT_hi[(size_t)DM*DM];
__device__ __nv_bfloat16 g_woutT_lo[(size_t)DM*DM];

// attention operands, bf16 hi/lo
__device__ __nv_bfloat16 g_qhi[(size_t)BH*SEQ*DH];
__device__ __nv_bfloat16 g_qlo[(size_t)BH*SEQ*DH];
__device__ __nv_bfloat16 g_khi[(size_t)BH*SEQ*DH];
__device__ __nv_bfloat16 g_klo[(size_t)BH*SEQ*DH];
__device__ __nv_bfloat16 g_vthi[(size_t)BH*DH*SEQ];   // [bh, d, s]
__device__ __nv_bfloat16 g_vtlo[(size_t)BH*DH*SEQ];

// ---------------- PTX helpers -------------------------------------------------
__device__ __forceinline__ uint32_t smem_u32(const void* p) {
    uint32_t a;
    asm("{ .reg .u64 t; cvta.to.shared.u64 t, %1; cvt.u32.u64 %0, t; }" : "=r"(a) : "l"(p));
    return a;
}
#define CP_ASYNC16(dst, src) \
    asm volatile("cp.async.cg.shared.global [%0], [%1], 16;" :: "r"(dst), "l"(src))
#define CP_COMMIT() asm volatile("cp.async.commit_group;" ::: "memory")
#define CP_WAIT(n)  asm volatile("cp.async.wait_group %0;" :: "n"(n) : "memory")

__device__ __forceinline__ void ldsm_x4(uint32_t* r, uint32_t addr) {
    asm volatile("ldmatrix.sync.aligned.m8n8.x4.shared.b16 {%0,%1,%2,%3}, [%4];"
        : "=r"(r[0]), "=r"(r[1]), "=r"(r[2]), "=r"(r[3]) : "r"(addr));
}
__device__ __forceinline__ void mma_bf16(float* d, const uint32_t* a,
                                         uint32_t b0, uint32_t b1) {
    asm volatile("mma.sync.aligned.m16n8k16.row.col.f32.bf16.bf16.f32 "
        "{%0,%1,%2,%3}, {%4,%5,%6,%7}, {%8,%9}, {%0,%1,%2,%3};"
        : "+f"(d[0]), "+f"(d[1]), "+f"(d[2]), "+f"(d[3])
        : "r"(a[0]), "r"(a[1]), "r"(a[2]), "r"(a[3]), "r"(b0), "r"(b1));
}
__device__ __forceinline__ void pack_hilo(float x, float y, uint32_t& hi, uint32_t& lo) {
    __nv_bfloat162 h = __floats2bfloat162_rn(x, y);
    float rx = x - __bfloat162float(h.x);
    float ry = y - __bfloat162float(h.y);
    __nv_bfloat162 l = __floats2bfloat162_rn(rx, ry);
    hi = *reinterpret_cast<uint32_t*>(&h);
    lo = *reinterpret_cast<uint32_t*>(&l);
}

// ---------------- split / transpose-split kernels ----------------------------
__global__ void split_a(const float* __restrict__ in,
                        __nv_bfloat16* __restrict__ hi,
                        __nv_bfloat16* __restrict__ lo, int n4)
{
    int i = blockIdx.x * blockDim.x + threadIdx.x;
    if (i >= n4) return;
    float4 v = ((const float4*)in)[i];
    uint32_t h0, l0, h1, l1;
    pack_hilo(v.x, v.y, h0, l0);
    pack_hilo(v.z, v.w, h1, l1);
    ((uint32_t*)hi)[i*2]   = h0;  ((uint32_t*)hi)[i*2+1] = h1;
    ((uint32_t*)lo)[i*2]   = l0;  ((uint32_t*)lo)[i*2+1] = l1;
}

// W[R,C] fp32 -> T[C,R] bf16 hi/lo
__global__ void transpose_split(const float* __restrict__ W,
                                __nv_bfloat16* __restrict__ Thi,
                                __nv_bfloat16* __restrict__ Tlo, int R, int C)
{
    __shared__ float t[32][33];
    int c0 = blockIdx.x * 32, r0 = blockIdx.y * 32;
    int tx = threadIdx.x, ty = threadIdx.y;
#pragma unroll
    for (int j = 0; j < 4; j++)
        t[ty + j*8][tx] = W[(size_t)(r0 + ty + j*8) * C + c0 + tx];
    __syncthreads();
#pragma unroll
    for (int j = 0; j < 4; j++) {
        int cc = c0 + ty + j*8;
        float v = t[tx][ty + j*8];
        __nv_bfloat16 h = __float2bfloat16(v);
        __nv_bfloat16 l = __float2bfloat16(v - __bfloat162float(h));
        Thi[(size_t)cc * R + r0 + tx] = h;
        Tlo[(size_t)cc * R + r0 + tx] = l;
    }
}

// V slice of g_qkv -> [bh, d, s] bf16 hi/lo
__global__ void v_transpose(const float* __restrict__ qkv)
{
    __shared__ float t[32][33];
    const int b = blockIdx.z >> 4, h = blockIdx.z & 15;
    const int d0 = blockIdx.x * 32, s0 = blockIdx.y * 32;
    const int tx = threadIdx.x, ty = threadIdx.y;
#pragma unroll
    for (int j = 0; j < 4; j++)
        t[ty + j*8][tx] = qkv[(size_t)(b * SEQ + s0 + ty + j*8) * QKVN
                              + 2*DM + h*DH + d0 + tx];
    __syncthreads();
#pragma unroll
    for (int j = 0; j < 4; j++) {
        int dd = d0 + ty + j*8;
        float v = t[tx][ty + j*8];                     // V[s0+tx][dd]
        __nv_bfloat16 hh = __float2bfloat16(v);
        __nv_bfloat16 ll = __float2bfloat16(v - __bfloat162float(hh));
        size_t o = ((size_t)blockIdx.z * DH + dd) * SEQ + s0 + tx;
        g_vthi[o] = hh;
        g_vtlo[o] = ll;
    }
}

// ---------------- RoPE -> bf16 hi/lo Q,K [bh,s,d] ----------------------------
__global__ void rope_split(const float* __restrict__ qkv,
                           const float* __restrict__ rc,
                           const float* __restrict__ rs)
{
    const int idx = blockIdx.x * blockDim.x + threadIdx.x;
    const int j = idx & (RH - 1);
    const int s = (idx >> 6) & (SEQ - 1);
    const int h = (idx >> 17) & (NH - 1);
    const int b = idx >> 21;

    const float* row = qkv + (size_t)(b * SEQ + s) * QKVN;
    const float c  = rc[s * RH + j];
    const float sn = rs[s * RH + j];
    const int col = h * DH + 2 * j;

    const float qe = row[col],      qo = row[col + 1];
    const float ke = row[DM + col], ko = row[DM + col + 1];

    const float q0 = qe * c - qo * sn, q1 = qe * sn + qo * c;
    const float k0 = ke * c - ko * sn, k1 = ke * sn + ko * c;

    const size_t o2 = (((size_t)((b * NH + h) * SEQ + s)) * DH + 2 * j) >> 1;
    uint32_t hi, lo;
    pack_hilo(q0, q1, hi, lo);
    ((uint32_t*)g_qhi)[o2] = hi; ((uint32_t*)g_qlo)[o2] = lo;
    pack_hilo(k0, k1, hi, lo);
    ((uint32_t*)g_khi)[o2] = hi; ((uint32_t*)g_klo)[o2] = lo;
}

// ---------------- bf16x3 GEMM via mma.sync (unchanged from R3) ---------------
#define TK 32
#define STR 80
#define T_TILE (128*STR)
#define STAGE  (4*T_TILE)
#define GEMM_SMEM (2*STAGE)

__global__ __launch_bounds__(256)
void gemm_tc(const __nv_bfloat16* __restrict__ Ahi, const __nv_bfloat16* __restrict__ Alo,
             const __nv_bfloat16* __restrict__ Bhi, const __nv_bfloat16* __restrict__ Blo,
             const float* __restrict__ bias, float* __restrict__ C,
             int M, int N, int K)
{
    extern __shared__ char sm[];
    const uint32_t sbase = smem_u32(sm);

    const int tid = threadIdx.x;
    const int wid = tid >> 5;
    const int lane = tid & 31;
    const int warpM = wid >> 2;
    const int warpN = wid & 3;
    const int bn = blockIdx.x * 128;
    const int bm = blockIdx.y * 128;

    const __nv_bfloat16* srcs[4] = {Ahi, Alo, Bhi, Blo};
    const int rowb[4] = {bm, bm, bn, bn};

    float acc[4][4][4];
#pragma unroll
    for (int mi = 0; mi < 4; mi++)
#pragma unroll
        for (int ni = 0; ni < 4; ni++)
#pragma unroll
            for (int r = 0; r < 4; r++) acc[mi][ni][r] = 0.f;

    const int NI = K / TK;

    {
#pragma unroll
        for (int it = 0; it < 8; it++) {
            int idx = it * 256 + tid;
            int t = idx >> 9, rem = idx & 511, r = rem >> 2, c = rem & 3;
            uint32_t dst = sbase + t * T_TILE + r * STR + c * 16;
            const void* src = srcs[t] + (size_t)(rowb[t] + r) * K + c * 8;
            CP_ASYNC16(dst, src);
        }
        CP_COMMIT();
    }

    for (int i = 0; i < NI; i++) {
        if (i + 1 < NI) {
            const int kt = (i + 1) * TK;
            const uint32_t st = sbase + ((i + 1) & 1) * STAGE;
#pragma unroll
            for (int it = 0; it < 8; it++) {
                int idx = it * 256 + tid;
                int t = idx >> 9, rem = idx & 511, r = rem >> 2, c = rem & 3;
                uint32_t dst = st + t * T_TILE + r * STR + c * 16;
                const void* src = srcs[t] + (size_t)(rowb[t] + r) * K + kt + c * 8;
                CP_ASYNC16(dst, src);
            }
            CP_COMMIT();
            CP_WAIT(1);
        } else {
            CP_WAIT(0);
        }
        __syncthreads();

        const uint32_t st = sbase + (i & 1) * STAGE;
        const uint32_t Ah = st, Al = st + T_TILE;
        const uint32_t Bh = st + 2 * T_TILE, Bl = st + 3 * T_TILE;

#pragma unroll
        for (int ks = 0; ks < 2; ks++) {
            const uint32_t ko = ks * 32 + (lane >> 4) * 16;
            const uint32_t arow = (warpM * 64 + (lane & 15)) * STR + ko;
            const uint32_t brow = (warpN * 32 + (lane & 15)) * STR + ko;

            uint32_t ahf[4][4], alf[4][4], bhf[2][4], blf[2][4];
#pragma unroll
            for (int mi = 0; mi < 4; mi++) {
                ldsm_x4(ahf[mi], Ah + arow + mi * 16 * STR);
                ldsm_x4(alf[mi], Al + arow + mi * 16 * STR);
            }
#pragma unroll
            for (int pi = 0; pi < 2; pi++) {
                ldsm_x4(bhf[pi], Bh + brow + pi * 16 * STR);
                ldsm_x4(blf[pi], Bl + brow + pi * 16 * STR);
            }
#pragma unroll
            for (int mi = 0; mi < 4; mi++)
#pragma unroll
                for (int ni = 0; ni < 4; ni++) {
                    const int pi = ni >> 1, o = ni & 1;
                    mma_bf16(acc[mi][ni], ahf[mi], bhf[pi][o], bhf[pi][o + 2]);
                    mma_bf16(acc[mi][ni], ahf[mi], blf[pi][o], blf[pi][o + 2]);
                    mma_bf16(acc[mi][ni], alf[mi], bhf[pi][o], bhf[pi][o + 2]);
                }
        }
        __syncthreads();
    }

#pragma unroll
    for (int mi = 0; mi < 4; mi++) {
        const int r0 = bm + warpM * 64 + mi * 16 + (lane >> 2);
#pragma unroll
        for (int ni = 0; ni < 4; ni++) {
            const int c0 = bn + warpN * 32 + ni * 8 + (lane & 3) * 2;
            const float b0 = bias[c0], b1 = bias[c0 + 1];
            float2 v0 = make_float2(acc[mi][ni][0] + b0, acc[mi][ni][1] + b1);
            float2 v1 = make_float2(acc[mi][ni][2] + b0, acc[mi][ni][3] + b1);
            *(float2*)(C + (size_t)r0 * N + c0) = v0;
            *(float2*)(C + (size_t)(r0 + 8) * N + c0) = v1;
        }
    }
}

// ---------------- HMMA flash attention ---------------------------------------
// CTA: 128 q rows (8 warps x 16), KV chunks of 64, bf16x3 everywhere.
#define KSTR 272                 // 128 bf16 = 256B + 16 pad
#define VSTR 144                 // 64 bf16 = 128B + 16 pad
#define KTILE (64*KSTR)          // 17408
#define VTILE (128*VSTR)         // 18432
#define ASTAGE (2*KTILE + 2*VTILE)   // 71680
#define QSTR 272
#define QTILE (128*QSTR)         // 34816
#define ATTN_SMEM (2*QTILE + 2*ASTAGE)  // 212992

__device__ __forceinline__ void attn_load_kv(uint32_t st, int bh, int k0, int tid)
{
    const __nv_bfloat16* kh = g_khi;
    const __nv_bfloat16* kl = g_klo;
    const __nv_bfloat16* vh = g_vthi;
    const __nv_bfloat16* vl = g_vtlo;
#pragma unroll
    for (int it = 0; it < 16; it++) {
        int idx = it * 256 + tid;
        int sec = idx >> 10, rem = idx & 1023;
        if (sec < 2) {
            int r = rem >> 4, c = rem & 15;
            uint32_t dst = st + sec * KTILE + r * KSTR + c * 16;
            const void* src = (sec ? kl : kh) + ((size_t)bh * SEQ + k0 + r) * DH + c * 8;
            CP_ASYNC16(dst, src);
        } else {
            int r = rem >> 3, c = rem & 7;
            uint32_t dst = st + 2 * KTILE + (sec - 2) * VTILE + r * VSTR + c * 16;
            const void* src = (sec == 2 ? vh : vl) + ((size_t)bh * DH + r) * SEQ + k0 + c * 8;
            CP_ASYNC16(dst, src);
        }
    }
}

__global__ __launch_bounds__(256, 1)
void attn_hmma()
{
    extern __shared__ char sm[];
    const uint32_t sbase = smem_u32(sm);
    const uint32_t qb_smem = sbase;
    const uint32_t stage0 = sbase + 2 * QTILE;

    const int qb = 15 - blockIdx.x;           // heavy tiles first
    const int h = blockIdx.y, b = blockIdx.z;
    const int bh = b * NH + h;
    const int q0 = qb * 128;
    const int tid = threadIdx.x;
    const int w = tid >> 5;
    const int lane = tid & 31;
    const float scale = 0.08838834764831845f; // 1/sqrt(128)

    // ---- stage Q into smem, ldmatrix fragments into registers
#pragma unroll
    for (int it = 0; it < 16; it++) {
        int idx = it * 256 + tid;
        int sec = idx >> 11, rem = idx & 2047;
        int r = rem >> 4, c = rem & 15;
        uint32_t dst = qb_smem + sec * QTILE + r * QSTR + c * 16;
        const void* src = (sec ? g_qlo : g_qhi) + ((size_t)bh * SEQ + q0 + r) * DH + c * 8;
        CP_ASYNC16(dst, src);
    }
    CP_COMMIT();
    CP_WAIT(0);
    __syncthreads();

    uint32_t qh[8][4], ql[8][4];
    {
        const uint32_t arow = (w * 16 + (lane & 15)) * QSTR + (lane >> 4) * 16;
#pragma unroll
        for (int kt = 0; kt < 8; kt++) {
            ldsm_x4(qh[kt], qb_smem + arow + kt * 32);
            ldsm_x4(ql[kt], qb_smem + QTILE + arow + kt * 32);
        }
    }

    float oa[16][4];
#pragma unroll
    for (int dt = 0; dt < 16; dt++)
#pragma unroll
        for (int r = 0; r < 4; r++) oa[dt][r] = 0.f;
    float m0 = -1e30f, m1 = -1e30f, l0 = 0.f, l1 = 0.f;

    const int nch = 2 * qb + 2;

    attn_load_kv(stage0, bh, 0, tid);
    CP_COMMIT();

    for (int kb = 0; kb < nch; kb++) {
        if (kb + 1 < nch) {
            attn_load_kv(stage0 + ((kb + 1) & 1) * ASTAGE, bh, (kb + 1) * 64, tid);
            CP_COMMIT();
            CP_WAIT(1);
        } else {
            CP_WAIT(0);
        }
        __syncthreads();

        const uint32_t st = stage0 + (kb & 1) * ASTAGE;
        const int k0 = kb * 64;

        // ---- scores: S = Qhi*Khi + Qhi*Klo + Qlo*Khi  (16x64 per warp)
        float e[8][4];
#pragma unroll
        for (int nt = 0; nt < 8; nt++)
#pragma unroll
            for (int r = 0; r < 4; r++) e[nt][r] = 0.f;

#pragma unroll
        for (int kt = 0; kt < 8; kt++) {
            const uint32_t ko = kt * 32 + (lane >> 4) * 16;
#pragma unroll
            for (int np = 0; np < 4; np++) {
                const uint32_t brow = (np * 16 + (lane & 15)) * KSTR + ko;
                uint32_t bhf[4], blf[4];
                ldsm_x4(bhf, st + brow);
                ldsm_x4(blf, st + KTILE + brow);
#pragma unroll
                for (int o = 0; o < 2; o++) {
                    const int nt = 2 * np + o;
                    mma_bf16(e[nt], qh[kt], bhf[o], bhf[o + 2]);
                    mma_bf16(e[nt], qh[kt], blf[o], blf[o + 2]);
                    mma_bf16(e[nt], ql[kt], bhf[o], bhf[o + 2]);
                }
            }
        }

        // scale + causal mask
#pragma unroll
        for (int nt = 0; nt < 8; nt++)
#pragma unroll
            for (int r = 0; r < 4; r++) e[nt][r] *= scale;

        const int row0 = q0 + w * 16 + (lane >> 2);
        if (kb >= 2 * qb) {
#pragma unroll
            for (int nt = 0; nt < 8; nt++) {
                const int col = k0 + nt * 8 + (lane & 3) * 2;
                if (col     > row0)     e[nt][0] = -1e30f;
                if (col + 1 > row0)     e[nt][1] = -1e30f;
                if (col     > row0 + 8) e[nt][2] = -1e30f;
                if (col + 1 > row0 + 8) e[nt][3] = -1e30f;
            }
        }

        // ---- online softmax (rows spread over lane&3 group)
        float rm0 = e[0][0], rm1 = e[0][2];
#pragma unroll
        for (int nt = 0; nt < 8; nt++) {
            rm0 = fmaxf(rm0, fmaxf(e[nt][0], e[nt][1]));
            rm1 = fmaxf(rm1, fmaxf(e[nt][2], e[nt][3]));
        }
        rm0 = fmaxf(rm0, __shfl_xor_sync(0xffffffffu, rm0, 1));
        rm0 = fmaxf(rm0, __shfl_xor_sync(0xffffffffu, rm0, 2));
        rm1 = fmaxf(rm1, __shfl_xor_sync(0xffffffffu, rm1, 1));
        rm1 = fmaxf(rm1, __shfl_xor_sync(0xffffffffu, rm1, 2));

        const float mn0 = fmaxf(m0, rm0), mn1 = fmaxf(m1, rm1);
        const float al0 = __expf(m0 - mn0), al1 = __expf(m1 - mn1);
        m0 = mn0; m1 = mn1;

        float s0 = 0.f, s1 = 0.f;
#pragma unroll
        for (int nt = 0; nt < 8; nt++) {
            e[nt][0] = __expf(e[nt][0] - mn0);
            e[nt][1] = __expf(e[nt][1] - mn0);
            e[nt][2] = __expf(e[nt][2] - mn1);
            e[nt][3] = __expf(e[nt][3] - mn1);
            s0 += e[nt][0] + e[nt][1];
            s1 += e[nt][2] + e[nt][3];
        }
        s0 += __shfl_xor_sync(0xffffffffu, s0, 1);
        s0 += __shfl_xor_sync(0xffffffffu, s0, 2);
        s1 += __shfl_xor_sync(0xffffffffu, s1, 1);
        s1 += __shfl_xor_sync(0xffffffffu, s1, 2);
        l0 = l0 * al0 + s0;
        l1 = l1 * al1 + s1;

#pragma unroll
        for (int dt = 0; dt < 16; dt++) {
            oa[dt][0] *= al0; oa[dt][1] *= al0;
            oa[dt][2] *= al1; oa[dt][3] *= al1;
        }

        // ---- O += Phi*Vhi + Phi*Vlo + Plo*Vhi   (V^T in smem, [d][s])
        const uint32_t vb = st + 2 * KTILE;
#pragma unroll
        for (int kt2 = 0; kt2 < 4; kt2++) {
            const int ta = 2 * kt2, tb = ta + 1;
            uint32_t ph[4], pl[4];
            pack_hilo(e[ta][0], e[ta][1], ph[0], pl[0]);
            pack_hilo(e[ta][2], e[ta][3], ph[1], pl[1]);
            pack_hilo(e[tb][0], e[tb][1], ph[2], pl[2]);
            pack_hilo(e[tb][2], e[tb][3], ph[3], pl[3]);

            const uint32_t ko = kt2 * 32 + (lane >> 4) * 16;
#pragma unroll
            for (int np = 0; np < 8; np++) {
                const uint32_t brow = (np * 16 + (lane & 15)) * VSTR + ko;
                uint32_t bhf[4], blf[4];
                ldsm_x4(bhf, vb + brow);
                ldsm_x4(blf, vb + VTILE + brow);
#pragma unroll
                for (int o = 0; o < 2; o++) {
                    const int dt = 2 * np + o;
                    mma_bf16(oa[dt], ph, bhf[o], bhf[o + 2]);
                    mma_bf16(oa[dt], ph, blf[o], blf[o + 2]);
                    mma_bf16(oa[dt], pl, bhf[o], bhf[o + 2]);
                }
            }
        }
        __syncthreads();
    }

    // ---- epilogue: write hi/lo bf16 directly (feeds out-proj GEMM)
    const float inv0 = 1.f / l0, inv1 = 1.f / l1;
    const size_t tokA = (size_t)b * SEQ + q0 + w * 16 + (lane >> 2);
    const size_t tokB = tokA + 8;
    const int colb = h * DH + (lane & 3) * 2;
    uint32_t* ahi = (uint32_t*)g_ahi;
    uint32_t* alo = (uint32_t*)g_alo;
#pragma unroll
    for (int dt = 0; dt < 16; dt++) {
        const int col = colb + dt * 8;
        uint32_t hi, lo;
        pack_hilo(oa[dt][0] * inv0, oa[dt][1] * inv0, hi, lo);
        ahi[(tokA * DM + col) >> 1] = hi;
        alo[(tokA * DM + col) >> 1] = lo;
        pack_hilo(oa[dt][2] * inv1, oa[dt][3] * inv1, hi, lo);
        ahi[(tokB * DM + col) >> 1] = hi;
        alo[(tokB * DM + col) >> 1] = lo;
    }
}

// ---------------- launch -----------------------------------------------------
extern "C" void kernel_launch(void* const* d_in, const int* in_sizes, int n_in,
                              void* d_out, int out_size)
{
    const float* x     = (const float*)d_in[0];
    const float* w_qkv = (const float*)d_in[1];
    const float* b_qkv = (const float*)d_in[2];
    const float* w_out = (const float*)d_in[3];
    const float* b_out = (const float*)d_in[4];
    const float* rc    = (const float*)d_in[5];
    const float* rs    = (const float*)d_in[6];
    float* out = (float*)d_out;

    float* p_qkv;
    __nv_bfloat16 *p_xhi, *p_xlo, *p_ahi, *p_alo;
    __nv_bfloat16 *p_wqh, *p_wql, *p_woh, *p_wol;
    cudaGetSymbolAddress((void**)&p_qkv, g_qkv);
    cudaGetSymbolAddress((void**)&p_xhi, g_xhi);
    cudaGetSymbolAddress((void**)&p_xlo, g_xlo);
    cudaGetSymbolAddress((void**)&p_ahi, g_ahi);
    cudaGetSymbolAddress((void**)&p_alo, g_alo);
    cudaGetSymbolAddress((void**)&p_wqh, g_wqkvT_hi);
    cudaGetSymbolAddress((void**)&p_wql, g_wqkvT_lo);
    cudaGetSymbolAddress((void**)&p_woh, g_woutT_hi);
    cudaGetSymbolAddress((void**)&p_wol, g_woutT_lo);

    cudaFuncSetAttribute(gemm_tc,
                         cudaFuncAttributeMaxDynamicSharedMemorySize, GEMM_SMEM);
    cudaFuncSetAttribute(attn_hmma,
                         cudaFuncAttributeMaxDynamicSharedMemorySize, ATTN_SMEM);

    // 1) split x -> bf16 hi/lo
    {
        int n4 = NTOK * DM / 4;
        split_a<<<(n4 + 255) / 256, 256>>>(x, p_xhi, p_xlo, n4);
    }
    // 2) transpose+split weights
    transpose_split<<<dim3(QKVN / 32, DM / 32), dim3(32, 8)>>>(w_qkv, p_wqh, p_wql, DM, QKVN);
    transpose_split<<<dim3(DM / 32, DM / 32), dim3(32, 8)>>>(w_out, p_woh, p_wol, DM, DM);
    // 3) qkv = x @ w_qkv + b  (HMMA bf16x3)
    gemm_tc<<<dim3(QKVN / 128, NTOK / 128), 256, GEMM_SMEM>>>(
        p_xhi, p_xlo, p_wqh, p_wql, b_qkv, p_qkv, NTOK, QKVN, DM);
    // 4) RoPE -> bf16 hi/lo Q,K ; V transpose -> [bh,d,s]
    rope_split<<<(BATCH * NH * SEQ * RH) / 256, 256>>>(p_qkv, rc, rs);
    v_transpose<<<dim3(DH / 32, SEQ / 32, BH), dim3(32, 8)>>>(p_qkv);
    // 5) HMMA flash attention -> g_ahi/g_alo
    attn_hmma<<<dim3(SEQ / 128, NH, BATCH), 256, ATTN_SMEM>>>();
    // 6) out = att @ w_out + b  (HMMA bf16x3)
    gemm_tc<<<dim3(DM / 128, NTOK / 128), 256, GEMM_SMEM>>>(
        p_ahi, p_alo, p_woh, p_wol, b_out, out, NTOK, DM, DM);
}